// round 4
// baseline (speedup 1.0000x reference)
#include <cuda_runtime.h>

// TCLWithoutParametersLoss: B=65536, D=512, C=21
//   e_j = 0.5*||c_j||^2 - f.c_j      (0.5||f||^2 cancels in pos-neg)
//   loss = mean( relu(e_label + 5 - min_{j!=label} e_j) )
//
// R4 design (fixing R3's smem-crossbar bound):
//  - 148 persistent blocks x 128 threads (4 warps/SM); block owns 442/443 rows
//  - each thread register-tiles R=4 rows; acc = 21x4 packed f32x2 (168 regs)
//  - centers read via UNIFORM LDG.128 (1 line/wavefront, L1-resident 43KB)
//    instead of broadcast LDS (which cost 4 crossbar cyc per 16B) -> L1 traffic /4
//  - features streamed with __ldcs (evict-first) and staged through smem in
//    32-float chunks, 512 rows x 9 float4 (144B stride = conflict-free LDS.128)
//  - dots via packed fma.rn.f32x2 -> fma-pipe bound ~43K cyc/SMSP (~22us)
//  - labels dtype runtime-probe (int32 vs int64 low-word) as in R3
//  - block reduce + atomicAdd(double); last block writes mean, resets state

#define NB      148
#define NT      128
#define BATCH   65536
#define DIMS    512
#define NC      21
#define MARGINF 5.0f
#define RQ      4              // rows per thread
#define DS_N    16             // 16 double-stages x 32 floats = 512
#define RSTRIDE 9              // float4 per staged row (8 data + 1 pad)

__device__ double       g_sum_d  = 0.0;
__device__ unsigned int g_done_d = 0u;

__device__ __forceinline__ unsigned long long ffma2(unsigned long long a,
                                                    unsigned long long b,
                                                    unsigned long long c) {
    unsigned long long r;
    asm("fma.rn.f32x2 %0, %1, %2, %3;" : "=l"(r) : "l"(a), "l"(b), "l"(c));
    return r;
}

extern __shared__ float4 smem4[];
// [0, 4608)        stage buf 0 (512 rows * 9 float4 = 73728 B)
// [4608, 9216)     stage buf 1
// total 147456 B dynamic

__global__ void __launch_bounds__(NT, 1)
tcl_kernel(const float* __restrict__ features,
           const float* __restrict__ centers,
           const int*   __restrict__ labels32,
           float* __restrict__ out)
{
    float4* buf0 = smem4;
    float4* buf1 = smem4 + 512 * RSTRIDE;

    __shared__ float s_hc2[NC];
    __shared__ float s_red[NT / 32];
    __shared__ int   s_is32;

    const int tid  = threadIdx.x;
    const int bid  = blockIdx.x;
    const int wid  = tid >> 5;
    const int lane = tid & 31;

    if (tid == 0) s_is32 = 0;
    __syncthreads();

    // labels dtype probe: odd words 1..255 (valid under both layouts).
    // int64 labels in [0,21) => odd words all zero; int32 => ~random labels.
    if (labels32[2 * tid + 1] != 0) s_is32 = 1;   // benign race

    // 0.5*||c_j||^2 : warp w handles centers w, w+4, ... ; 32 lanes x 4 float4.
    // (also warms centers into L1 before the main loop)
    const float4* c4 = (const float4*)centers;
    for (int j = wid; j < NC; j += 4) {
        float s = 0.f;
        #pragma unroll
        for (int q = 0; q < 4; q++) {
            float4 v = c4[j * 128 + q * 32 + lane];
            s += v.x * v.x + v.y * v.y + v.z * v.z + v.w * v.w;
        }
        #pragma unroll
        for (int off = 16; off; off >>= 1)
            s += __shfl_down_sync(0xffffffffu, s, off);
        if (lane == 0) s_hc2[j] = 0.5f * s;
    }

    // row range: exact balance 443*120 + 442*28 = 65536
    const int base = bid * 442 + min(bid, 120);
    const int cnt  = 442 + (bid < 120 ? 1 : 0);

    const float4*     f4 = (const float4*)features;
    const ulonglong2* cu = (const ulonglong2*)centers;

    unsigned long long acc[RQ][NC];
    #pragma unroll
    for (int rr = 0; rr < RQ; rr++)
        #pragma unroll
        for (int j = 0; j < NC; j++) acc[rr][j] = 0ull;

    // ---- staging: double-stage ds covers floats [ds*32, ds*32+32) of each row
    // layout: dst[row*9 + q], q in 0..7 (float4). Coalesced LDG: warp covers
    // 4 rows x 128B full lines. __ldcs keeps centers resident in L1.
    {
        #pragma unroll
        for (int i = 0; i < 32; i++) {
            int idx = tid + i * NT;
            int row = idx >> 3, q = idx & 7;
            int srow = min(row, cnt - 1);
            buf0[row * RSTRIDE + q] = __ldcs(&f4[(size_t)(base + srow) * 128 + q]);
        }
    }

    for (int ds = 0; ds < DS_N; ds++) {
        __syncthreads();
        if (ds + 1 < DS_N) {
            float4* dst = (ds & 1) ? buf0 : buf1;
            const int koff = (ds + 1) * 8;
            #pragma unroll
            for (int i = 0; i < 32; i++) {
                int idx = tid + i * NT;
                int row = idx >> 3, q = idx & 7;
                int srow = min(row, cnt - 1);
                dst[row * RSTRIDE + q] =
                    __ldcs(&f4[(size_t)(base + srow) * 128 + koff + q]);
            }
        }
        const float4* cur = (ds & 1) ? buf1 : buf0;

        #pragma unroll
        for (int kk = 0; kk < 4; kk++) {           // 8-float sub-chunks
            ulonglong2 f[RQ][2];
            #pragma unroll
            for (int rr = 0; rr < RQ; rr++) {
                const ulonglong2* fp =
                    (const ulonglong2*)(cur + (tid + rr * NT) * RSTRIDE + kk * 2);
                f[rr][0] = fp[0];
                f[rr][1] = fp[1];
            }
            #pragma unroll
            for (int j = 0; j < NC; j++) {
                // uniform LDG.128 x2: all lanes same address -> 1 line each
                ulonglong2 c0 = cu[j * 128 + ds * 8 + kk * 2];
                ulonglong2 c1 = cu[j * 128 + ds * 8 + kk * 2 + 1];
                #pragma unroll
                for (int rr = 0; rr < RQ; rr++) {
                    unsigned long long a = acc[rr][j];
                    a = ffma2(f[rr][0].x, c0.x, a);
                    a = ffma2(f[rr][0].y, c0.y, a);
                    a = ffma2(f[rr][1].x, c1.x, a);
                    a = ffma2(f[rr][1].y, c1.y, a);
                    acc[rr][j] = a;
                }
            }
        }
    }

    __syncthreads();

    // ---- epilogue: e_j, pos/neg, hinge for each of this thread's rows ----
    float myloss = 0.f;
    #pragma unroll
    for (int rr = 0; rr < RQ; rr++) {
        int row = tid + rr * NT;
        if (row < cnt) {
            int g   = base + row;
            int lab = s_is32 ? labels32[g] : labels32[2 * g];
            float pos = 0.f;
            float neg = 3.402823466e38f;
            #pragma unroll
            for (int j = 0; j < NC; j++) {
                float lo  = __uint_as_float((unsigned)(acc[rr][j] & 0xffffffffull));
                float hi  = __uint_as_float((unsigned)(acc[rr][j] >> 32));
                float e   = s_hc2[j] - (lo + hi);
                if (j == lab) pos = e;
                else          neg = fminf(neg, e);
            }
            myloss += fmaxf(pos + MARGINF - neg, 0.f);
        }
    }

    // ---- block reduction: 4 warps -> 4 partials -> warp 0 ----
    #pragma unroll
    for (int off = 16; off; off >>= 1)
        myloss += __shfl_down_sync(0xffffffffu, myloss, off);
    if (lane == 0) s_red[wid] = myloss;
    __syncthreads();
    if (tid == 0) {
        float v = s_red[0] + s_red[1] + s_red[2] + s_red[3];
        atomicAdd(&g_sum_d, (double)v);
        __threadfence();
        unsigned p = atomicAdd(&g_done_d, 1u);
        if (p == NB - 1) {                 // last block finalizes
            __threadfence();
            double total = atomicAdd(&g_sum_d, 0.0);
            *out = (float)(total * (1.0 / (double)BATCH));
            g_sum_d = 0.0;
            __threadfence();
            g_done_d = 0u;
        }
    }
}

extern "C" void kernel_launch(void* const* d_in, const int* in_sizes, int n_in,
                              void* d_out, int out_size) {
    const float* features = (const float*)d_in[0];
    const float* centers  = (const float*)d_in[1];
    const int*   labels   = (const int*)d_in[2];

    size_t shmem = (size_t)(2 * 512 * RSTRIDE) * sizeof(float4);  // 147456 B
    cudaFuncSetAttribute(tcl_kernel,
                         cudaFuncAttributeMaxDynamicSharedMemorySize, (int)shmem);
    tcl_kernel<<<NB, NT, shmem>>>(features, centers, labels, (float*)d_out);
}

// round 7
// speedup vs baseline: 2.0654x; 2.0654x over previous
#include <cuda_runtime.h>
#include <cstdint>

// TCLWithoutParametersLoss: B=65536, D=512, C=21
//   e_j = 0.5*||c_j||^2 - f.c_j      (0.5||f||^2 cancels in pos-neg)
//   loss = mean( relu(e_label + 5 - min_{j!=label} e_j) )
//
// R5 (fix R4's register spill: regs=255 -> occ 6.3%):
//  - 148 persistent blocks x 256 threads (8 warps/SM); block owns 442/443 rows
//  - RQ=2 rows/thread -> acc 21x2 packed f32x2 = 84 regs (fits, no spill)
//  - centers via uniform LDG.128 (1 line/wavefront, 43KB L1-resident)
//  - features staged to smem with cp.async.cg (no staging regs, no STS,
//    L1-bypass so centers stay resident); 512 rows x 9-float4 stride
//    (144B: conflict-free 8-lane LDS.128 phases)
//  - dots via packed fma.rn.f32x2; fma-pipe bound ~43K cyc/SMSP (~22us)
//  - labels dtype runtime-probe (int32 vs int64 low-word)
//  - block reduce + atomicAdd(double); last block writes mean, resets state

#define NB      148
#define NT      256
#define BATCH   65536
#define DIMS    512
#define NC      21
#define MARGINF 5.0f
#define RQ      2              // rows per thread
#define DS_N    16             // 16 double-stages x 32 floats = 512
#define RSTRIDE 9              // float4 per staged row (8 data + 1 pad)

__device__ double       g_sum_d  = 0.0;
__device__ unsigned int g_done_d = 0u;

__device__ __forceinline__ unsigned long long ffma2(unsigned long long a,
                                                    unsigned long long b,
                                                    unsigned long long c) {
    unsigned long long r;
    asm("fma.rn.f32x2 %0, %1, %2, %3;" : "=l"(r) : "l"(a), "l"(b), "l"(c));
    return r;
}

__device__ __forceinline__ uint32_t smem_u32(const void* p) {
    uint32_t a;
    asm("{ .reg .u64 t; cvta.to.shared.u64 t, %1; cvt.u32.u64 %0, t; }"
        : "=r"(a) : "l"(p));
    return a;
}

__device__ __forceinline__ void cp_async16(uint32_t dst, const void* src) {
    asm volatile("cp.async.cg.shared.global [%0], [%1], 16;"
                 :: "r"(dst), "l"(src));
}
#define CP_COMMIT() asm volatile("cp.async.commit_group;")
#define CP_WAIT(N)  asm volatile("cp.async.wait_group %0;" :: "n"(N))

extern __shared__ float4 smem4[];
// [0, 4608)        stage buf 0 (512 rows * 9 float4 = 73728 B)
// [4608, 9216)     stage buf 1
// total 147456 B dynamic

__global__ void __launch_bounds__(NT)
tcl_kernel(const float* __restrict__ features,
           const float* __restrict__ centers,
           const int*   __restrict__ labels32,
           float* __restrict__ out)
{
    float4* buf0 = smem4;
    float4* buf1 = smem4 + 512 * RSTRIDE;

    __shared__ float s_hc2[NC];
    __shared__ float s_red[NT / 32];
    __shared__ int   s_is32;

    const int tid  = threadIdx.x;
    const int bid  = blockIdx.x;
    const int wid  = tid >> 5;
    const int lane = tid & 31;

    if (tid == 0) s_is32 = 0;
    __syncthreads();

    // labels dtype probe: odd words 1..511 (valid under both layouts).
    // int64 labels in [0,21) => odd words all zero; int32 => ~random labels.
    if (labels32[2 * tid + 1] != 0) s_is32 = 1;   // benign race

    // row range: exact balance 443*120 + 442*28 = 65536
    const int base = bid * 442 + min(bid, 120);
    const int cnt  = 442 + (bid < 120 ? 1 : 0);

    const float4* f4 = (const float4*)features;
    const uint32_t b0u = smem_u32(buf0);
    const uint32_t b1u = smem_u32(buf1);

    // ---- prologue: stage 0 into buf0 via cp.async ----
    {
        #pragma unroll
        for (int i = 0; i < 16; i++) {
            int idx = tid + i * NT;
            int row = idx >> 3, q = idx & 7;
            int srow = min(row, cnt - 1);
            cp_async16(b0u + (uint32_t)(row * RSTRIDE + q) * 16u,
                       &f4[(size_t)(base + srow) * 128 + q]);
        }
        CP_COMMIT();
    }

    // 0.5*||c_j||^2 : warp w handles centers w, w+8, ... (overlaps with cp.async;
    // also warms centers into L1 before the main loop)
    const float4* c4 = (const float4*)centers;
    for (int j = wid; j < NC; j += 8) {
        float s = 0.f;
        #pragma unroll
        for (int q = 0; q < 4; q++) {
            float4 v = c4[j * 128 + q * 32 + lane];
            s += v.x * v.x + v.y * v.y + v.z * v.z + v.w * v.w;
        }
        #pragma unroll
        for (int off = 16; off; off >>= 1)
            s += __shfl_down_sync(0xffffffffu, s, off);
        if (lane == 0) s_hc2[j] = 0.5f * s;
    }

    const ulonglong2* cu = (const ulonglong2*)centers;

    unsigned long long acc[RQ][NC];
    #pragma unroll
    for (int rr = 0; rr < RQ; rr++)
        #pragma unroll
        for (int j = 0; j < NC; j++) acc[rr][j] = 0ull;

    for (int ds = 0; ds < DS_N; ds++) {
        // kick stage ds+1 into the other buffer
        if (ds + 1 < DS_N) {
            uint32_t dstu = (ds & 1) ? b0u : b1u;
            const int koff = (ds + 1) * 8;
            #pragma unroll
            for (int i = 0; i < 16; i++) {
                int idx = tid + i * NT;
                int row = idx >> 3, q = idx & 7;
                int srow = min(row, cnt - 1);
                cp_async16(dstu + (uint32_t)(row * RSTRIDE + q) * 16u,
                           &f4[(size_t)(base + srow) * 128 + koff + q]);
            }
            CP_COMMIT();
            CP_WAIT(1);          // stage ds complete (ds+1 still in flight)
        } else {
            CP_WAIT(0);
        }
        __syncthreads();

        const float4* cur = (ds & 1) ? buf1 : buf0;

        #pragma unroll
        for (int kk = 0; kk < 4; kk++) {           // 8-float sub-chunks
            ulonglong2 f[RQ][2];
            #pragma unroll
            for (int rr = 0; rr < RQ; rr++) {
                const ulonglong2* fp =
                    (const ulonglong2*)(cur + (tid + rr * NT) * RSTRIDE + kk * 2);
                f[rr][0] = fp[0];
                f[rr][1] = fp[1];
            }
            #pragma unroll
            for (int j = 0; j < NC; j++) {
                // uniform LDG.128 x2: all lanes same address -> L1 hit, 1 line each
                ulonglong2 c0 = cu[j * 128 + ds * 8 + kk * 2];
                ulonglong2 c1 = cu[j * 128 + ds * 8 + kk * 2 + 1];
                #pragma unroll
                for (int rr = 0; rr < RQ; rr++) {
                    unsigned long long a = acc[rr][j];
                    a = ffma2(f[rr][0].x, c0.x, a);
                    a = ffma2(f[rr][0].y, c0.y, a);
                    a = ffma2(f[rr][1].x, c1.x, a);
                    a = ffma2(f[rr][1].y, c1.y, a);
                    acc[rr][j] = a;
                }
            }
        }
        __syncthreads();   // done reading cur before next issue overwrites it
    }

    // ---- epilogue: e_j, pos/neg, hinge for each of this thread's rows ----
    float myloss = 0.f;
    #pragma unroll
    for (int rr = 0; rr < RQ; rr++) {
        int row = tid + rr * NT;
        if (row < cnt) {
            int g   = base + row;
            int lab = s_is32 ? labels32[g] : labels32[2 * g];
            float pos = 0.f;
            float neg = 3.402823466e38f;
            #pragma unroll
            for (int j = 0; j < NC; j++) {
                float lo  = __uint_as_float((unsigned)(acc[rr][j] & 0xffffffffull));
                float hi  = __uint_as_float((unsigned)(acc[rr][j] >> 32));
                float e   = s_hc2[j] - (lo + hi);
                if (j == lab) pos = e;
                else          neg = fminf(neg, e);
            }
            myloss += fmaxf(pos + MARGINF - neg, 0.f);
        }
    }

    // ---- block reduction: 8 warps -> partials -> thread 0 ----
    #pragma unroll
    for (int off = 16; off; off >>= 1)
        myloss += __shfl_down_sync(0xffffffffu, myloss, off);
    if (lane == 0) s_red[wid] = myloss;
    __syncthreads();
    if (tid == 0) {
        float v = 0.f;
        #pragma unroll
        for (int w = 0; w < NT / 32; w++) v += s_red[w];
        atomicAdd(&g_sum_d, (double)v);
        __threadfence();
        unsigned p = atomicAdd(&g_done_d, 1u);
        if (p == NB - 1) {                 // last block finalizes
            __threadfence();
            double total = atomicAdd(&g_sum_d, 0.0);
            *out = (float)(total * (1.0 / (double)BATCH));
            g_sum_d = 0.0;
            __threadfence();
            g_done_d = 0u;
        }
    }
}

extern "C" void kernel_launch(void* const* d_in, const int* in_sizes, int n_in,
                              void* d_out, int out_size) {
    const float* features = (const float*)d_in[0];
    const float* centers  = (const float*)d_in[1];
    const int*   labels   = (const int*)d_in[2];

    size_t shmem = (size_t)(2 * 512 * RSTRIDE) * sizeof(float4);  // 147456 B
    cudaFuncSetAttribute(tcl_kernel,
                         cudaFuncAttributeMaxDynamicSharedMemorySize, (int)shmem);
    tcl_kernel<<<NB, NT, shmem>>>(features, centers, labels, (float*)d_out);
}

// round 11
// speedup vs baseline: 2.2666x; 1.0974x over previous
#include <cuda_runtime.h>
#include <cstdint>

// TCLWithoutParametersLoss: B=65536, D=512, C=21
//   e_j = 0.5*||c_j||^2 - f.c_j      (0.5||f||^2 cancels in pos-neg)
//   loss = mean( relu(e_label + 5 - min_{j!=label} e_j) )
//
// R8 (cut center-reload L1 traffic, which bound R7 at 64.6% L1):
//  - 148 persistent blocks x 128 threads (1 warp/SMSP); block owns 442/443 rows
//  - RQ=4 rows/thread: 21x4 packed-f32x2 accumulators (168 regs). No spill this
//    time: staging is cp.async (zero staging registers) unlike R4's 32-deep LDG.
//  - per center j: ONE uniform LDG.128 feeds 32 FFMA2 -> 64 fma-busy cycles
//    hide the 39-cyc L1-hit latency even at 1 warp/SMSP (next-c preloaded)
//  - center LDG count halved vs R7: 4 warps x 2688 = 10.7K/SM
//  - features staged via cp.async.cg double-buffer, 512 rows x 9-float4 stride
//  - labels dtype runtime-probe (int32 vs int64 low-word)
//  - block reduce + atomicAdd(double); last block writes mean, resets state

#define NB      148
#define NT      128
#define BATCH   65536
#define DIMS    512
#define NC      21
#define MARGINF 5.0f
#define RQ      4              // rows per thread
#define DS_N    16             // 16 double-stages x 32 floats = 512
#define RSTRIDE 9              // float4 per staged row (8 data + 1 pad)

__device__ double       g_sum_d  = 0.0;
__device__ unsigned int g_done_d = 0u;

__device__ __forceinline__ unsigned long long ffma2(unsigned long long a,
                                                    unsigned long long b,
                                                    unsigned long long c) {
    unsigned long long r;
    asm("fma.rn.f32x2 %0, %1, %2, %3;" : "=l"(r) : "l"(a), "l"(b), "l"(c));
    return r;
}

__device__ __forceinline__ uint32_t smem_u32(const void* p) {
    uint32_t a;
    asm("{ .reg .u64 t; cvta.to.shared.u64 t, %1; cvt.u32.u64 %0, t; }"
        : "=r"(a) : "l"(p));
    return a;
}

__device__ __forceinline__ void cp_async16(uint32_t dst, const void* src) {
    asm volatile("cp.async.cg.shared.global [%0], [%1], 16;"
                 :: "r"(dst), "l"(src));
}
#define CP_COMMIT() asm volatile("cp.async.commit_group;")
#define CP_WAIT(N)  asm volatile("cp.async.wait_group %0;" :: "n"(N))

extern __shared__ float4 smem4[];
// [0, 4608)        stage buf 0 (512 rows * 9 float4 = 73728 B)
// [4608, 9216)     stage buf 1
// total 147456 B dynamic

__global__ void __launch_bounds__(NT, 1)
tcl_kernel(const float* __restrict__ features,
           const float* __restrict__ centers,
           const int*   __restrict__ labels32,
           float* __restrict__ out)
{
    float4* buf0 = smem4;
    float4* buf1 = smem4 + 512 * RSTRIDE;

    __shared__ float s_hc2[NC];
    __shared__ float s_red[NT / 32];
    __shared__ int   s_is32;

    const int tid  = threadIdx.x;
    const int bid  = blockIdx.x;
    const int wid  = tid >> 5;
    const int lane = tid & 31;

    if (tid == 0) s_is32 = 0;
    __syncthreads();

    // labels dtype probe: odd words 1..255 (valid under both layouts).
    // int64 labels in [0,21) => odd words all zero; int32 => ~random labels.
    if (labels32[2 * tid + 1] != 0) s_is32 = 1;   // benign race

    // row range: exact balance 443*120 + 442*28 = 65536
    const int base = bid * 442 + min(bid, 120);
    const int cnt  = 442 + (bid < 120 ? 1 : 0);

    const float4* f4 = (const float4*)features;
    const uint32_t b0u = smem_u32(buf0);
    const uint32_t b1u = smem_u32(buf1);

    // ---- prologue: stage 0 into buf0 via cp.async (32 per thread) ----
    {
        #pragma unroll
        for (int i = 0; i < 32; i++) {
            int idx = tid + i * NT;
            int row = idx >> 3, q = idx & 7;
            int srow = min(row, cnt - 1);
            cp_async16(b0u + (uint32_t)(row * RSTRIDE + q) * 16u,
                       &f4[(size_t)(base + srow) * 128 + q]);
        }
        CP_COMMIT();
    }

    // 0.5*||c_j||^2 : warp w handles centers w, w+4, ... (overlaps cp.async;
    // also warms centers into L1)
    const float4* c4 = (const float4*)centers;
    for (int j = wid; j < NC; j += 4) {
        float s = 0.f;
        #pragma unroll
        for (int q = 0; q < 4; q++) {
            float4 v = c4[j * 128 + q * 32 + lane];
            s += v.x * v.x + v.y * v.y + v.z * v.z + v.w * v.w;
        }
        #pragma unroll
        for (int off = 16; off; off >>= 1)
            s += __shfl_down_sync(0xffffffffu, s, off);
        if (lane == 0) s_hc2[j] = 0.5f * s;
    }

    const ulonglong2* cu = (const ulonglong2*)centers;

    unsigned long long acc[RQ][NC];
    #pragma unroll
    for (int rr = 0; rr < RQ; rr++)
        #pragma unroll
        for (int j = 0; j < NC; j++) acc[rr][j] = 0ull;

    for (int ds = 0; ds < DS_N; ds++) {
        // kick stage ds+1 into the other buffer
        if (ds + 1 < DS_N) {
            uint32_t dstu = (ds & 1) ? b0u : b1u;
            const int koff = (ds + 1) * 8;
            #pragma unroll
            for (int i = 0; i < 32; i++) {
                int idx = tid + i * NT;
                int row = idx >> 3, q = idx & 7;
                int srow = min(row, cnt - 1);
                cp_async16(dstu + (uint32_t)(row * RSTRIDE + q) * 16u,
                           &f4[(size_t)(base + srow) * 128 + koff + q]);
            }
            CP_COMMIT();
            CP_WAIT(1);          // stage ds complete (ds+1 still in flight)
        } else {
            CP_WAIT(0);
        }
        __syncthreads();

        const float4* cur = (ds & 1) ? buf1 : buf0;

        #pragma unroll
        for (int kk = 0; kk < 8; kk++) {           // 4-float sub-chunks
            // per-row feature chunk (LDS.128, 144B lane stride: conflict-free)
            ulonglong2 f[RQ];
            #pragma unroll
            for (int rr = 0; rr < RQ; rr++)
                f[rr] = *(const ulonglong2*)(cur + (tid + rr * NT) * RSTRIDE + kk);

            // software-pipelined center stream: one uniform LDG.128 per j
            ulonglong2 c = cu[0 * 128 + ds * 8 + kk];
            #pragma unroll
            for (int j = 0; j < NC; j++) {
                ulonglong2 cn;
                if (j + 1 < NC) cn = cu[(j + 1) * 128 + ds * 8 + kk];
                #pragma unroll
                for (int rr = 0; rr < RQ; rr++) {
                    unsigned long long a = acc[rr][j];
                    a = ffma2(f[rr].x, c.x, a);
                    a = ffma2(f[rr].y, c.y, a);
                    acc[rr][j] = a;
                }
                c = cn;
            }
        }
        __syncthreads();   // done reading cur before next stage overwrites it
    }

    // ---- epilogue: e_j, pos/neg, hinge for each of this thread's rows ----
    float myloss = 0.f;
    #pragma unroll
    for (int rr = 0; rr < RQ; rr++) {
        int row = tid + rr * NT;
        if (row < cnt) {
            int g   = base + row;
            int lab = s_is32 ? labels32[g] : labels32[2 * g];
            float pos = 0.f;
            float neg = 3.402823466e38f;
            #pragma unroll
            for (int j = 0; j < NC; j++) {
                float lo  = __uint_as_float((unsigned)(acc[rr][j] & 0xffffffffull));
                float hi  = __uint_as_float((unsigned)(acc[rr][j] >> 32));
                float e   = s_hc2[j] - (lo + hi);
                if (j == lab) pos = e;
                else          neg = fminf(neg, e);
            }
            myloss += fmaxf(pos + MARGINF - neg, 0.f);
        }
    }

    // ---- block reduction: 4 warps -> partials -> thread 0 ----
    #pragma unroll
    for (int off = 16; off; off >>= 1)
        myloss += __shfl_down_sync(0xffffffffu, myloss, off);
    if (lane == 0) s_red[wid] = myloss;
    __syncthreads();
    if (tid == 0) {
        float v = s_red[0] + s_red[1] + s_red[2] + s_red[3];
        atomicAdd(&g_sum_d, (double)v);
        __threadfence();
        unsigned p = atomicAdd(&g_done_d, 1u);
        if (p == NB - 1) {                 // last block finalizes
            __threadfence();
            double total = atomicAdd(&g_sum_d, 0.0);
            *out = (float)(total * (1.0 / (double)BATCH));
            g_sum_d = 0.0;
            __threadfence();
            g_done_d = 0u;
        }
    }
}

extern "C" void kernel_launch(void* const* d_in, const int* in_sizes, int n_in,
                              void* d_out, int out_size) {
    const float* features = (const float*)d_in[0];
    const float* centers  = (const float*)d_in[1];
    const int*   labels   = (const int*)d_in[2];

    size_t shmem = (size_t)(2 * 512 * RSTRIDE) * sizeof(float4);  // 147456 B
    cudaFuncSetAttribute(tcl_kernel,
                         cudaFuncAttributeMaxDynamicSharedMemorySize, (int)shmem);
    tcl_kernel<<<NB, NT, shmem>>>(features, centers, labels, (float*)d_out);
}

// round 13
// speedup vs baseline: 2.5735x; 1.1354x over previous
#include <cuda_runtime.h>
#include <cstdint>

// TCLWithoutParametersLoss: B=65536, D=512, C=21
//   e_j = 0.5*||c_j||^2 - f.c_j      (0.5||f||^2 cancels in pos-neg)
//   loss = mean( relu(e_label + 5 - min_{j!=label} e_j) )
//
// R12 (break R11's regs-vs-warps deadlock):
//  - 148 blocks x 256 threads. Thread-half g = tid>>7 handles 11 centers:
//    g0 -> j 0..10, g1 -> j 10..20 (overlap at 10: identical unrolled NJ=11
//    loop in both halves, no divergence; duplicate j=10 harmless under min).
//  - RQ=4 rows/thread kept (center-load ratio of R8) but acc = 11x4 packed
//    f32x2 = 88 regs -> no spill AND 2 warps/SMSP to hide latency.
//  - centers via uniform LDG.128, 2-deep preload (32 fma-cyc cover/center).
//  - features staged via cp.async.cg double-buffer, 512 rows x 9-float4.
//  - per-row {pos,neg} halves merged through smem at the end.
//  - labels dtype runtime-probe (int32 vs int64 low-word).
//  - block reduce + atomicAdd(double); last block writes mean, resets state.

#define NB      148
#define NT      256
#define HALF    128
#define BATCH   65536
#define DIMS    512
#define NC      21
#define NJ      11             // centers per half (overlap at j=10)
#define MARGINF 5.0f
#define RQ      4              // rows per thread
#define DS_N    16             // 16 double-stages x 32 floats = 512
#define RSTRIDE 9              // float4 per staged row (8 data + 1 pad)
#define FINF    3.402823466e38f

__device__ double       g_sum_d  = 0.0;
__device__ unsigned int g_done_d = 0u;

__device__ __forceinline__ unsigned long long ffma2(unsigned long long a,
                                                    unsigned long long b,
                                                    unsigned long long c) {
    unsigned long long r;
    asm("fma.rn.f32x2 %0, %1, %2, %3;" : "=l"(r) : "l"(a), "l"(b), "l"(c));
    return r;
}

__device__ __forceinline__ uint32_t smem_u32(const void* p) {
    uint32_t a;
    asm("{ .reg .u64 t; cvta.to.shared.u64 t, %1; cvt.u32.u64 %0, t; }"
        : "=r"(a) : "l"(p));
    return a;
}

__device__ __forceinline__ void cp_async16(uint32_t dst, const void* src) {
    asm volatile("cp.async.cg.shared.global [%0], [%1], 16;"
                 :: "r"(dst), "l"(src));
}
#define CP_COMMIT() asm volatile("cp.async.commit_group;")
#define CP_WAIT(N)  asm volatile("cp.async.wait_group %0;" :: "n"(N))

extern __shared__ float4 smem4[];
// [0, 4608)        stage buf 0 (512 rows * 9 float4 = 73728 B)
// [4608, 9216)     stage buf 1
// total 147456 B dynamic; result float2[1024] reuses buf0 after main loop

__global__ void __launch_bounds__(NT, 1)
tcl_kernel(const float* __restrict__ features,
           const float* __restrict__ centers,
           const int*   __restrict__ labels32,
           float* __restrict__ out)
{
    float4* buf0 = smem4;
    float4* buf1 = smem4 + 512 * RSTRIDE;

    __shared__ float s_hc2[NC];
    __shared__ float s_red[NT / 32];
    __shared__ int   s_is32;

    const int tid  = threadIdx.x;
    const int bid  = blockIdx.x;
    const int wid  = tid >> 5;
    const int lane = tid & 31;
    const int g    = tid >> 7;          // center-half: 0 or 1
    const int gtid = tid & (HALF - 1);  // row slot within half
    const int j0   = g * 10;            // g0: 0..10, g1: 10..20

    if (tid == 0) s_is32 = 0;
    __syncthreads();

    // labels dtype probe: odd words 1..511 (valid under both layouts).
    // int64 labels in [0,21) => odd words all zero; int32 => ~random labels.
    if (labels32[2 * tid + 1] != 0) s_is32 = 1;   // benign race

    // row range: exact balance 443*120 + 442*28 = 65536
    const int base = bid * 442 + min(bid, 120);
    const int cnt  = 442 + (bid < 120 ? 1 : 0);

    const float4* f4 = (const float4*)features;
    const uint32_t b0u = smem_u32(buf0);
    const uint32_t b1u = smem_u32(buf1);

    // ---- prologue: stage 0 into buf0 via cp.async (16 per thread) ----
    {
        #pragma unroll
        for (int i = 0; i < 16; i++) {
            int idx = tid + i * NT;
            int row = idx >> 3, q = idx & 7;
            int srow = min(row, cnt - 1);
            cp_async16(b0u + (uint32_t)(row * RSTRIDE + q) * 16u,
                       &f4[(size_t)(base + srow) * 128 + q]);
        }
        CP_COMMIT();
    }

    // 0.5*||c_j||^2 : warp w handles centers w, w+8, ... (overlaps cp.async;
    // also warms centers into L1)
    const float4* c4 = (const float4*)centers;
    for (int j = wid; j < NC; j += 8) {
        float s = 0.f;
        #pragma unroll
        for (int q = 0; q < 4; q++) {
            float4 v = c4[j * 128 + q * 32 + lane];
            s += v.x * v.x + v.y * v.y + v.z * v.z + v.w * v.w;
        }
        #pragma unroll
        for (int off = 16; off; off >>= 1)
            s += __shfl_down_sync(0xffffffffu, s, off);
        if (lane == 0) s_hc2[j] = 0.5f * s;
    }

    const ulonglong2* cu = (const ulonglong2*)centers + (size_t)j0 * 128;

    unsigned long long acc[RQ][NJ];
    #pragma unroll
    for (int rr = 0; rr < RQ; rr++)
        #pragma unroll
        for (int jj = 0; jj < NJ; jj++) acc[rr][jj] = 0ull;

    for (int ds = 0; ds < DS_N; ds++) {
        // kick stage ds+1 into the other buffer
        if (ds + 1 < DS_N) {
            uint32_t dstu = (ds & 1) ? b0u : b1u;
            const int koff = (ds + 1) * 8;
            #pragma unroll
            for (int i = 0; i < 16; i++) {
                int idx = tid + i * NT;
                int row = idx >> 3, q = idx & 7;
                int srow = min(row, cnt - 1);
                cp_async16(dstu + (uint32_t)(row * RSTRIDE + q) * 16u,
                           &f4[(size_t)(base + srow) * 128 + koff + q]);
            }
            CP_COMMIT();
            CP_WAIT(1);          // stage ds complete (ds+1 still in flight)
        } else {
            CP_WAIT(0);
        }
        __syncthreads();

        const float4* cur = (ds & 1) ? buf1 : buf0;

        #pragma unroll
        for (int kk = 0; kk < 8; kk++) {           // 4-float sub-chunks
            // per-row feature chunk (LDS.128, 144B lane stride: conflict-free)
            ulonglong2 f[RQ];
            #pragma unroll
            for (int rr = 0; rr < RQ; rr++)
                f[rr] = *(const ulonglong2*)(cur + (gtid + rr * HALF) * RSTRIDE + kk);

            // center stream: uniform LDG.128, 2-deep preload
            const ulonglong2* cb = cu + ds * 8 + kk;
            ulonglong2 c0 = cb[0];
            ulonglong2 c1 = cb[128];
            #pragma unroll
            for (int jj = 0; jj < NJ; jj++) {
                ulonglong2 cn;
                if (jj + 2 < NJ) cn = cb[(size_t)(jj + 2) * 128];
                #pragma unroll
                for (int rr = 0; rr < RQ; rr++) {
                    unsigned long long a = acc[rr][jj];
                    a = ffma2(f[rr].x, c0.x, a);
                    a = ffma2(f[rr].y, c0.y, a);
                    acc[rr][jj] = a;
                }
                c0 = c1;
                c1 = cn;
            }
        }
        __syncthreads();   // done reading cur before next stage overwrites it
    }

    // ---- epilogue: per-half {pos, neg} into smem, then merge halves ----
    __syncthreads();
    float2* res = (float2*)smem4;   // 1024 float2 = 8KB (staging bufs dead)

    #pragma unroll
    for (int rr = 0; rr < RQ; rr++) {
        int row  = gtid + rr * HALF;
        int srow = min(row, cnt - 1);
        int gr   = base + srow;
        int lab  = s_is32 ? labels32[gr] : labels32[2 * gr];
        float pos = FINF;
        float neg = FINF;
        #pragma unroll
        for (int jj = 0; jj < NJ; jj++) {
            int j = j0 + jj;
            float lo = __uint_as_float((unsigned)(acc[rr][jj] & 0xffffffffull));
            float hi = __uint_as_float((unsigned)(acc[rr][jj] >> 32));
            float e  = s_hc2[j] - (lo + hi);
            if (j == lab) pos = e;
            else          neg = fminf(neg, e);
        }
        res[g * 512 + row] = make_float2(pos, neg);
    }
    __syncthreads();

    float myloss = 0.f;
    if (g == 0) {
        #pragma unroll
        for (int rr = 0; rr < RQ; rr++) {
            int row = gtid + rr * HALF;
            if (row < cnt) {
                float2 a = res[row];
                float2 b = res[512 + row];
                float pos = fminf(a.x, b.x);            // exactly one finite (or equal)
                float neg = fminf(a.y, b.y);
                myloss += fmaxf(pos + MARGINF - neg, 0.f);
            }
        }
    }

    // ---- block reduction: 8 warps (g1 contributes 0) ----
    #pragma unroll
    for (int off = 16; off; off >>= 1)
        myloss += __shfl_down_sync(0xffffffffu, myloss, off);
    if (lane == 0) s_red[wid] = myloss;
    __syncthreads();
    if (tid == 0) {
        float v = 0.f;
        #pragma unroll
        for (int w = 0; w < NT / 32; w++) v += s_red[w];
        atomicAdd(&g_sum_d, (double)v);
        __threadfence();
        unsigned p = atomicAdd(&g_done_d, 1u);
        if (p == NB - 1) {                 // last block finalizes
            __threadfence();
            double total = atomicAdd(&g_sum_d, 0.0);
            *out = (float)(total * (1.0 / (double)BATCH));
            g_sum_d = 0.0;
            __threadfence();
            g_done_d = 0u;
        }
    }
}

extern "C" void kernel_launch(void* const* d_in, const int* in_sizes, int n_in,
                              void* d_out, int out_size) {
    const float* features = (const float*)d_in[0];
    const float* centers  = (const float*)d_in[1];
    const int*   labels   = (const int*)d_in[2];

    size_t shmem = (size_t)(2 * 512 * RSTRIDE) * sizeof(float4);  // 147456 B
    cudaFuncSetAttribute(tcl_kernel,
                         cudaFuncAttributeMaxDynamicSharedMemorySize, (int)shmem);
    tcl_kernel<<<NB, NT, shmem>>>(features, centers, labels, (float*)d_out);
}